// round 1
// baseline (speedup 1.0000x reference)
#include <cuda_runtime.h>
#include <math.h>

// ---------------------------------------------------------------------------
// PosNegCrossAttention  (B=4, L=1024, E=1024, H=16, Dh=64)
// Output layout (flattened tuple, fp32):
//   [0)            pos_output  : 4*1024*1024      = 4194304
//   [4194304)      neg_output  : 4194304
//   [8388608)      pos_attn    : 4*16*1024*1024   = 67108864
//   [75497472)     neg_attn    : 67108864
// ---------------------------------------------------------------------------

#define M_ROWS 4096            // B*L
#define EDIM   1024
#define HEADS  16
#define DH     64
#define NROWS  65536           // B*H*L  (attention rows)

#define OFF_POSO 0
#define OFF_NEGO 4194304
#define OFF_POSA 8388608
#define OFF_NEGA 75497472

// Scratch (device globals: allocation-guard safe)
__device__ float g_Q [M_ROWS * EDIM];
__device__ float g_K [M_ROWS * EDIM];
__device__ float g_V [M_ROWS * EDIM];
__device__ float g_O1[M_ROWS * EDIM];   // pos head-space output [B*L, E]
__device__ float g_O2[M_ROWS * EDIM];   // neg head-space output

// ---------------------------------------------------------------------------
// Generic C = alpha * A @ B^T + bias   (A: MxK lda, B: NxK ldb, C: MxN ldc)
// 64x64 tile, 16x16 threads, 4x4 per thread, K-chunks of 16.
// ---------------------------------------------------------------------------
__global__ void gemm_abt_kernel(const float* __restrict__ A, int lda,
                                const float* __restrict__ Bm, int ldb,
                                const float* __restrict__ bias,
                                float* __restrict__ C, int ldc,
                                int Kdim, float alpha)
{
    __shared__ float As[64][17];
    __shared__ float Bs[64][17];
    const int tx = threadIdx.x, ty = threadIdx.y;
    const int tid = ty * 16 + tx;
    const int row0 = blockIdx.y * 64;
    const int col0 = blockIdx.x * 64;

    float acc[4][4] = {};

    for (int kk = 0; kk < Kdim; kk += 16) {
#pragma unroll
        for (int t = 0; t < 4; t++) {
            int li = tid + t * 256;
            int i = li >> 4, k = li & 15;
            As[i][k] = A [(size_t)(row0 + i) * lda + kk + k];
            Bs[i][k] = Bm[(size_t)(col0 + i) * ldb + kk + k];
        }
        __syncthreads();
#pragma unroll
        for (int k = 0; k < 16; k++) {
            float a[4], b[4];
#pragma unroll
            for (int i = 0; i < 4; i++) a[i] = As[ty * 4 + i][k];
#pragma unroll
            for (int j = 0; j < 4; j++) b[j] = Bs[tx * 4 + j][k];
#pragma unroll
            for (int i = 0; i < 4; i++)
#pragma unroll
                for (int j = 0; j < 4; j++)
                    acc[i][j] += a[i] * b[j];
        }
        __syncthreads();
    }

#pragma unroll
    for (int i = 0; i < 4; i++) {
        int r = row0 + ty * 4 + i;
#pragma unroll
        for (int j = 0; j < 4; j++) {
            int c = col0 + tx * 4 + j;
            float v = acc[i][j] * alpha;
            if (bias) v += bias[c];
            C[(size_t)r * ldc + c] = v;
        }
    }
}

// ---------------------------------------------------------------------------
// scores[b,h][q,k] = (1/8) * sum_d Q[b*L+q, h*64+d] * K[b*L+k, h*64+d]
// grid (16,16,64)  z = b*16+h.  Writes raw scores into pos_attn region.
// ---------------------------------------------------------------------------
__global__ void scores_kernel(const float* __restrict__ Q,
                              const float* __restrict__ Kp,
                              float* __restrict__ attn)
{
    const int z = blockIdx.z;
    const int b = z >> 4, h = z & 15;
    const float* A  = Q  + (size_t)b * (1024 * 1024) + h * 64;
    const float* Bm = Kp + (size_t)b * (1024 * 1024) + h * 64;
    float*       C  = attn + (size_t)z * (1024 * 1024);

    __shared__ float As[64][17];
    __shared__ float Bs[64][17];
    const int tx = threadIdx.x, ty = threadIdx.y;
    const int tid = ty * 16 + tx;
    const int row0 = blockIdx.y * 64;
    const int col0 = blockIdx.x * 64;

    float acc[4][4] = {};

    for (int kk = 0; kk < 64; kk += 16) {
#pragma unroll
        for (int t = 0; t < 4; t++) {
            int li = tid + t * 256;
            int i = li >> 4, k = li & 15;
            As[i][k] = A [(size_t)(row0 + i) * 1024 + kk + k];
            Bs[i][k] = Bm[(size_t)(col0 + i) * 1024 + kk + k];
        }
        __syncthreads();
#pragma unroll
        for (int k = 0; k < 16; k++) {
            float a[4], bb[4];
#pragma unroll
            for (int i = 0; i < 4; i++) a[i] = As[ty * 4 + i][k];
#pragma unroll
            for (int j = 0; j < 4; j++) bb[j] = Bs[tx * 4 + j][k];
#pragma unroll
            for (int i = 0; i < 4; i++)
#pragma unroll
                for (int j = 0; j < 4; j++)
                    acc[i][j] += a[i] * bb[j];
        }
        __syncthreads();
    }

#pragma unroll
    for (int i = 0; i < 4; i++) {
        int r = row0 + ty * 4 + i;
#pragma unroll
        for (int j = 0; j < 4; j++)
            C[(size_t)r * 1024 + col0 + tx * 4 + j] = acc[i][j] * 0.125f;
    }
}

// ---------------------------------------------------------------------------
// Per row (1024 keys): softmax -> pos_attn; neg chain -> neg_attn.
// One block per row, 256 threads. Raw scores read from pos region (in-place).
// ---------------------------------------------------------------------------
__device__ __forceinline__ float block_reduce_max(float v, float* red)
{
    int t = threadIdx.x;
    red[t] = v; __syncthreads();
    for (int s = 128; s > 0; s >>= 1) {
        if (t < s) red[t] = fmaxf(red[t], red[t + s]);
        __syncthreads();
    }
    float r = red[0]; __syncthreads();
    return r;
}

__device__ __forceinline__ float block_reduce_sum(float v, float* red)
{
    int t = threadIdx.x;
    red[t] = v; __syncthreads();
    for (int s = 128; s > 0; s >>= 1) {
        if (t < s) red[t] += red[t + s];
        __syncthreads();
    }
    float r = red[0]; __syncthreads();
    return r;
}

__global__ void softmax_neg_kernel(float* __restrict__ attnPos,
                                   float* __restrict__ attnNeg)
{
    const size_t rid = blockIdx.x;
    float* prow = attnPos + rid * 1024;
    float* nrow = attnNeg + rid * 1024;

    __shared__ float s[1024];
    __shared__ float red[256];
    const int t = threadIdx.x;

    float lmax = -1e30f;
#pragma unroll
    for (int i = t; i < 1024; i += 256) {
        float v = prow[i];
        s[i] = v;
        lmax = fmaxf(lmax, v);
    }
    const float m = block_reduce_max(lmax, red);

    float lsum = 0.f;
#pragma unroll
    for (int i = t; i < 1024; i += 256) {
        float e = __expf(s[i] - m);
        s[i] = e;
        lsum += e;
    }
    const float inv = 1.0f / block_reduce_sum(lsum, red);

    float l1 = 0.f;
#pragma unroll
    for (int i = t; i < 1024; i += 256) {
        float p = s[i] * inv;
        s[i] = p;
        l1 += (1.0f - p);
    }
    const float S1 = block_reduce_sum(l1, red);
    const float invS1 = 1.0f / S1;

    float l2 = 0.f;
#pragma unroll
    for (int i = t; i < 1024; i += 256) {
        float p = s[i];
        prow[i] = p;                                   // final pos_attn
        float n = (1.0f - p) * invS1;
        n = fminf(n, 1e-6f / (p + 1e-10f));
        s[i] = n;
        l2 += n;
    }
    const float inv2 = 1.0f / block_reduce_sum(l2, red);

#pragma unroll
    for (int i = t; i < 1024; i += 256)
        nrow[i] = s[i] * inv2;                          // final neg_attn
}

// ---------------------------------------------------------------------------
// O[b*L+q, h*64+d] = sum_k Attn[b,h][q,k] * V[b*L+k, h*64+d]
// grid (1,16,128): y = q-tile, z<64 -> pos, z>=64 -> neg; bh = z&63.
// ---------------------------------------------------------------------------
__global__ void attnv_kernel(const float* __restrict__ attnP,
                             const float* __restrict__ attnN,
                             const float* __restrict__ V,
                             float* __restrict__ O1,
                             float* __restrict__ O2)
{
    const int z = blockIdx.z;
    const int bh = z & 63;
    const int b = bh >> 4, h = bh & 15;
    const float* P  = (z < 64 ? attnP : attnN) + (size_t)bh * (1024 * 1024);
    const float* Vh = V + (size_t)b * (1024 * 1024) + h * 64;
    float*       O  = (z < 64 ? O1 : O2) + (size_t)b * (1024 * 1024) + h * 64;

    __shared__ float Ps[64][17];
    __shared__ float Vs[16][65];
    const int tx = threadIdx.x, ty = threadIdx.y;
    const int tid = ty * 16 + tx;
    const int row0 = blockIdx.y * 64;

    float acc[4][4] = {};

    for (int kk = 0; kk < 1024; kk += 16) {
#pragma unroll
        for (int t = 0; t < 4; t++) {
            int li = tid + t * 256;
            {   // P chunk: 64 x 16
                int i = li >> 4, k = li & 15;
                Ps[i][k] = P[(size_t)(row0 + i) * 1024 + kk + k];
            }
            {   // V chunk: 16 x 64
                int kc = li >> 6, d = li & 63;
                Vs[kc][d] = Vh[(size_t)(kk + kc) * 1024 + d];
            }
        }
        __syncthreads();
#pragma unroll
        for (int k = 0; k < 16; k++) {
            float a[4], bb[4];
#pragma unroll
            for (int i = 0; i < 4; i++) a[i] = Ps[ty * 4 + i][k];
#pragma unroll
            for (int j = 0; j < 4; j++) bb[j] = Vs[k][tx * 4 + j];
#pragma unroll
            for (int i = 0; i < 4; i++)
#pragma unroll
                for (int j = 0; j < 4; j++)
                    acc[i][j] += a[i] * bb[j];
        }
        __syncthreads();
    }

#pragma unroll
    for (int i = 0; i < 4; i++) {
        int r = row0 + ty * 4 + i;
#pragma unroll
        for (int j = 0; j < 4; j++)
            O[(size_t)r * 1024 + tx * 4 + j] = acc[i][j];
    }
}

// ---------------------------------------------------------------------------
// Launch
// ---------------------------------------------------------------------------
extern "C" void kernel_launch(void* const* d_in, const int* in_sizes, int n_in,
                              void* d_out, int out_size)
{
    const float* query = (const float*)d_in[0];
    const float* key   = (const float*)d_in[1];
    const float* value = (const float*)d_in[2];
    const float* Wq    = (const float*)d_in[3];
    const float* bq    = (const float*)d_in[4];
    const float* Wk    = (const float*)d_in[5];
    const float* bk    = (const float*)d_in[6];
    const float* Wv    = (const float*)d_in[7];
    const float* bv    = (const float*)d_in[8];
    const float* Wo    = (const float*)d_in[9];
    const float* bo    = (const float*)d_in[10];
    float* out = (float*)d_out;

    float *Q, *K, *V, *O1, *O2;
    cudaGetSymbolAddress((void**)&Q,  g_Q);
    cudaGetSymbolAddress((void**)&K,  g_K);
    cudaGetSymbolAddress((void**)&V,  g_V);
    cudaGetSymbolAddress((void**)&O1, g_O1);
    cudaGetSymbolAddress((void**)&O2, g_O2);

    dim3 blk(16, 16);
    dim3 gproj(EDIM / 64, M_ROWS / 64);          // (16, 64)

    // Projections: [4096,1024] = X @ W^T + b
    gemm_abt_kernel<<<gproj, blk>>>(query, EDIM, Wq, EDIM, bq, Q, EDIM, EDIM, 1.0f);
    gemm_abt_kernel<<<gproj, blk>>>(key,   EDIM, Wk, EDIM, bk, K, EDIM, EDIM, 1.0f);
    gemm_abt_kernel<<<gproj, blk>>>(value, EDIM, Wv, EDIM, bv, V, EDIM, EDIM, 1.0f);

    // Raw scores -> pos_attn region (scratch)
    dim3 gsc(16, 16, 64);
    scores_kernel<<<gsc, blk>>>(Q, K, out + OFF_POSA);

    // Softmax + neg chain (in-place pos, writes neg)
    softmax_neg_kernel<<<NROWS, 256>>>(out + OFF_POSA, out + OFF_NEGA);

    // Attn @ V for pos and neg
    dim3 gav(1, 16, 128);
    attnv_kernel<<<gav, blk>>>(out + OFF_POSA, out + OFF_NEGA, V, O1, O2);

    // Output projection
    gemm_abt_kernel<<<gproj, blk>>>(O1, EDIM, Wo, EDIM, bo, out + OFF_POSO, EDIM, EDIM, 1.0f);
    gemm_abt_kernel<<<gproj, blk>>>(O2, EDIM, Wo, EDIM, bo, out + OFF_NEGO, EDIM, EDIM, 1.0f);
}

// round 4
// speedup vs baseline: 2.5286x; 2.5286x over previous
#include <cuda_runtime.h>
#include <math.h>
#include <stdint.h>

// ---------------------------------------------------------------------------
// PosNegCrossAttention  (B=4, L=1024, E=1024, H=16, Dh=64)  — TF32 mma.sync
// Output layout (flattened tuple, fp32):
//   [0)         pos_output : 4194304
//   [4194304)   neg_output : 4194304
//   [8388608)   pos_attn   : 67108864
//   [75497472)  neg_attn   : 67108864
// ---------------------------------------------------------------------------

#define M_ROWS 4096
#define EDIM   1024
#define NROWS  65536

#define OFF_POSO 0
#define OFF_NEGO 4194304
#define OFF_POSA 8388608
#define OFF_NEGA 75497472

__device__ float g_Q [M_ROWS * EDIM];
__device__ float g_K [M_ROWS * EDIM];
__device__ float g_V [M_ROWS * EDIM];
__device__ float g_O1[M_ROWS * EDIM];
__device__ float g_O2[M_ROWS * EDIM];

// ---------------------------------------------------------------------------
// helpers
// ---------------------------------------------------------------------------
__device__ __forceinline__ uint32_t f2tf(float f)
{
    uint32_t u;
    asm("cvt.rna.tf32.f32 %0, %1;" : "=r"(u) : "f"(f));
    return u;
}

__device__ __forceinline__ void mma8(float* c, const uint32_t* a, const uint32_t* b)
{
    asm volatile(
        "mma.sync.aligned.m16n8k8.row.col.f32.tf32.tf32.f32 "
        "{%0,%1,%2,%3},{%4,%5,%6,%7},{%8,%9},{%0,%1,%2,%3};"
        : "+f"(c[0]), "+f"(c[1]), "+f"(c[2]), "+f"(c[3])
        : "r"(a[0]), "r"(a[1]), "r"(a[2]), "r"(a[3]), "r"(b[0]), "r"(b[1]));
}

// ---------------------------------------------------------------------------
// Generic batched TF32 GEMM.
//   C = alpha * A @ op(B) + bias
//   A: row-major M x K (lda)
//   B_KN=false: B stored as N x K (row-major)  -> C = A @ B^T
//   B_KN=true : B stored as K x N (row-major)  -> C = A @ B
// Per-z pointer offsets: off = (z/16)*s1 + (z%16)*s2
// ---------------------------------------------------------------------------
template<int BM, int BN, int BK, int WM, int WN, bool B_KN>
__global__ void gemm_tc(const float* __restrict__ A, int lda, long long sA1, long long sA2,
                        const float* __restrict__ B, int ldb, long long sB1, long long sB2,
                        const float* __restrict__ bias,
                        float* __restrict__ C, int ldc, long long sC1, long long sC2,
                        int Kdim, float alpha)
{
    constexpr int WARPS_M = BM / WM;
    constexpr int WARPS_N = BN / WN;
    constexpr int NTHREADS = WARPS_M * WARPS_N * 32;
    constexpr int MT = WM / 16;
    constexpr int NT = WN / 8;
    constexpr int PAD = 4;
    constexpr int BROWS = B_KN ? BK : BN;
    constexpr int BCOLS = (B_KN ? BN : BK) + PAD;

    const int z = blockIdx.z;
    A += (long long)(z >> 4) * sA1 + (long long)(z & 15) * sA2;
    B += (long long)(z >> 4) * sB1 + (long long)(z & 15) * sB2;
    C += (long long)(z >> 4) * sC1 + (long long)(z & 15) * sC2;

    __shared__ __align__(16) uint32_t As[BM][BK + PAD];
    __shared__ __align__(16) uint32_t Bs[BROWS][BCOLS];

    const int tid  = threadIdx.x;
    const int lane = tid & 31;
    const int warp = tid >> 5;
    const int wm = warp / WARPS_N;
    const int wn = warp % WARPS_N;
    const int row0 = blockIdx.y * BM;
    const int col0 = blockIdx.x * BN;

    float acc[MT][NT][4] = {};

    for (int kk = 0; kk < Kdim; kk += BK) {
        // ---- stage A (BM x BK) ----
        constexpr int A_F4 = BM * BK / 4;
#pragma unroll
        for (int i = tid; i < A_F4; i += NTHREADS) {
            int r  = i / (BK / 4);
            int c4 = i % (BK / 4);
            float4 v = *(const float4*)&A[(size_t)(row0 + r) * lda + kk + c4 * 4];
            uint4 u = make_uint4(f2tf(v.x), f2tf(v.y), f2tf(v.z), f2tf(v.w));
            *(uint4*)&As[r][c4 * 4] = u;
        }
        // ---- stage B ----
        if (!B_KN) {
            constexpr int B_F4 = BN * BK / 4;
#pragma unroll
            for (int i = tid; i < B_F4; i += NTHREADS) {
                int r  = i / (BK / 4);
                int c4 = i % (BK / 4);
                float4 v = *(const float4*)&B[(size_t)(col0 + r) * ldb + kk + c4 * 4];
                uint4 u = make_uint4(f2tf(v.x), f2tf(v.y), f2tf(v.z), f2tf(v.w));
                *(uint4*)&Bs[r][c4 * 4] = u;
            }
        } else {
            constexpr int B_F4 = BK * BN / 4;
#pragma unroll
            for (int i = tid; i < B_F4; i += NTHREADS) {
                int r  = i / (BN / 4);
                int c4 = i % (BN / 4);
                float4 v = *(const float4*)&B[(size_t)(kk + r) * ldb + col0 + c4 * 4];
                uint4 u = make_uint4(f2tf(v.x), f2tf(v.y), f2tf(v.z), f2tf(v.w));
                *(uint4*)&Bs[r][c4 * 4] = u;
            }
        }
        __syncthreads();

#pragma unroll
        for (int ks = 0; ks < BK; ks += 8) {
            uint32_t af[MT][4];
            uint32_t bf[NT][2];
#pragma unroll
            for (int mt = 0; mt < MT; mt++) {
                int m0 = wm * WM + mt * 16;
                af[mt][0] = As[m0 + (lane >> 2)    ][ks + (lane & 3)    ];
                af[mt][1] = As[m0 + (lane >> 2) + 8][ks + (lane & 3)    ];
                af[mt][2] = As[m0 + (lane >> 2)    ][ks + (lane & 3) + 4];
                af[mt][3] = As[m0 + (lane >> 2) + 8][ks + (lane & 3) + 4];
            }
#pragma unroll
            for (int nt = 0; nt < NT; nt++) {
                int n0 = wn * WN + nt * 8;
                if (!B_KN) {
                    bf[nt][0] = Bs[n0 + (lane >> 2)][ks + (lane & 3)    ];
                    bf[nt][1] = Bs[n0 + (lane >> 2)][ks + (lane & 3) + 4];
                } else {
                    bf[nt][0] = Bs[ks + (lane & 3)    ][n0 + (lane >> 2)];
                    bf[nt][1] = Bs[ks + (lane & 3) + 4][n0 + (lane >> 2)];
                }
            }
#pragma unroll
            for (int mt = 0; mt < MT; mt++)
#pragma unroll
                for (int nt = 0; nt < NT; nt++)
                    mma8(acc[mt][nt], af[mt], bf[nt]);
        }
        __syncthreads();
    }

    // ---- epilogue ----
#pragma unroll
    for (int mt = 0; mt < MT; mt++) {
#pragma unroll
        for (int nt = 0; nt < NT; nt++) {
            int r = row0 + wm * WM + mt * 16 + (lane >> 2);
            int c = col0 + wn * WN + nt * 8 + 2 * (lane & 3);
            float b0 = bias ? bias[c]     : 0.0f;
            float b1 = bias ? bias[c + 1] : 0.0f;
            C[(size_t)r * ldc + c]           = acc[mt][nt][0] * alpha + b0;
            C[(size_t)r * ldc + c + 1]       = acc[mt][nt][1] * alpha + b1;
            C[(size_t)(r + 8) * ldc + c]     = acc[mt][nt][2] * alpha + b0;
            C[(size_t)(r + 8) * ldc + c + 1] = acc[mt][nt][3] * alpha + b1;
        }
    }
}

// ---------------------------------------------------------------------------
// Warp-per-row softmax + neg chain, fully in registers (no barriers).
// 256 threads = 8 rows per block.  Row length 1024 = 32 floats per lane.
// ---------------------------------------------------------------------------
__global__ void softmax_neg_kernel(float* __restrict__ pos,
                                   float* __restrict__ neg)
{
    const int warp = threadIdx.x >> 5;
    const int lane = threadIdx.x & 31;
    const size_t rid = (size_t)blockIdx.x * 8 + warp;
    float* prow = pos + rid * 1024;
    float* nrow = neg + rid * 1024;

    float v[32];
#pragma unroll
    for (int j = 0; j < 32; j++) v[j] = prow[j * 32 + lane];

    float m = -1e30f;
#pragma unroll
    for (int j = 0; j < 32; j++) m = fmaxf(m, v[j]);
#pragma unroll
    for (int s = 16; s > 0; s >>= 1) m = fmaxf(m, __shfl_xor_sync(0xffffffffu, m, s));

    float sum = 0.f;
#pragma unroll
    for (int j = 0; j < 32; j++) { v[j] = __expf(v[j] - m); sum += v[j]; }
#pragma unroll
    for (int s = 16; s > 0; s >>= 1) sum += __shfl_xor_sync(0xffffffffu, sum, s);
    const float inv = 1.0f / sum;

    float s1 = 0.f;
#pragma unroll
    for (int j = 0; j < 32; j++) { v[j] *= inv; s1 += 1.0f - v[j]; }
#pragma unroll
    for (int s = 16; s > 0; s >>= 1) s1 += __shfl_xor_sync(0xffffffffu, s1, s);
    const float invS1 = 1.0f / s1;

    float s2 = 0.f;
#pragma unroll
    for (int j = 0; j < 32; j++) {
        float p = v[j];
        prow[j * 32 + lane] = p;                       // final pos_attn
        float n = fminf((1.0f - p) * invS1, 1e-6f / (p + 1e-10f));
        v[j] = n;
        s2 += n;
    }
#pragma unroll
    for (int s = 16; s > 0; s >>= 1) s2 += __shfl_xor_sync(0xffffffffu, s2, s);
    const float inv2 = 1.0f / s2;

#pragma unroll
    for (int j = 0; j < 32; j++)
        nrow[j * 32 + lane] = v[j] * inv2;             // final neg_attn
}

// ---------------------------------------------------------------------------
// Launch
// ---------------------------------------------------------------------------
extern "C" void kernel_launch(void* const* d_in, const int* in_sizes, int n_in,
                              void* d_out, int out_size)
{
    const float* query = (const float*)d_in[0];
    const float* key   = (const float*)d_in[1];
    const float* value = (const float*)d_in[2];
    const float* Wq    = (const float*)d_in[3];
    const float* bq    = (const float*)d_in[4];
    const float* Wk    = (const float*)d_in[5];
    const float* bk    = (const float*)d_in[6];
    const float* Wv    = (const float*)d_in[7];
    const float* bv    = (const float*)d_in[8];
    const float* Wo    = (const float*)d_in[9];
    const float* bo    = (const float*)d_in[10];
    float* out = (float*)d_out;

    float *Q, *K, *V, *O1, *O2;
    cudaGetSymbolAddress((void**)&Q,  g_Q);
    cudaGetSymbolAddress((void**)&K,  g_K);
    cudaGetSymbolAddress((void**)&V,  g_V);
    cudaGetSymbolAddress((void**)&O1, g_O1);
    cudaGetSymbolAddress((void**)&O2, g_O2);

    // -------- projections: [4096,1024] = X @ W^T + b --------
    dim3 gproj(EDIM / 128, M_ROWS / 128, 1);   // (8, 32)
    gemm_tc<128,128,32,64,32,false><<<gproj, 256>>>(
        query, EDIM, 0, 0,  Wq, EDIM, 0, 0,  bq,  Q, EDIM, 0, 0,  EDIM, 1.0f);
    gemm_tc<128,128,32,64,32,false><<<gproj, 256>>>(
        key,   EDIM, 0, 0,  Wk, EDIM, 0, 0,  bk,  K, EDIM, 0, 0,  EDIM, 1.0f);
    gemm_tc<128,128,32,64,32,false><<<gproj, 256>>>(
        value, EDIM, 0, 0,  Wv, EDIM, 0, 0,  bv,  V, EDIM, 0, 0,  EDIM, 1.0f);

    // -------- scores: per (b,h) Q K^T / 8 -> pos_attn region --------
    // A,B offsets: (z>>4)*1M + (z&15)*64 ; C offset: z*1M
    gemm_tc<128,128,32,64,32,false><<<dim3(8, 8, 64), 256>>>(
        Q, EDIM, 1048576, 64,
        K, EDIM, 1048576, 64,
        nullptr,
        out + OFF_POSA, 1024, 16777216, 1048576,
        64, 0.125f);

    // -------- softmax + neg chain --------
    softmax_neg_kernel<<<NROWS / 8, 256>>>(out + OFF_POSA, out + OFF_NEGA);

    // -------- attn @ V (pos and neg) --------
    // A (attn) offset: z*1M ; B (V), C (O) offsets: (z>>4)*1M + (z&15)*64
    gemm_tc<64,64,32,32,32,true><<<dim3(1, 16, 64), 128>>>(
        out + OFF_POSA, 1024, 16777216, 1048576,
        V, EDIM, 1048576, 64,
        nullptr,
        O1, EDIM, 1048576, 64,
        1024, 1.0f);
    gemm_tc<64,64,32,32,32,true><<<dim3(1, 16, 64), 128>>>(
        out + OFF_NEGA, 1024, 16777216, 1048576,
        V, EDIM, 1048576, 64,
        nullptr,
        O2, EDIM, 1048576, 64,
        1024, 1.0f);

    // -------- output projection --------
    gemm_tc<128,128,32,64,32,false><<<gproj, 256>>>(
        O1, EDIM, 0, 0,  Wo, EDIM, 0, 0,  bo,  out + OFF_POSO, EDIM, 0, 0,  EDIM, 1.0f);
    gemm_tc<128,128,32,64,32,false><<<gproj, 256>>>(
        O2, EDIM, 0, 0,  Wo, EDIM, 0, 0,  bo,  out + OFF_NEGO, EDIM, 0, 0,  EDIM, 1.0f);
}

// round 11
// speedup vs baseline: 3.2768x; 1.2959x over previous
#include <cuda_runtime.h>
#include <math.h>
#include <stdint.h>

// ---------------------------------------------------------------------------
// PosNegCrossAttention  (B=4, L=1024, E=1024, H=16, Dh=64)  — TF32 mma.sync
// R5: double-buffered, register-staged GEMM mainloop (1 sync per K-tile).
// Output layout (flattened tuple, fp32):
//   [0)         pos_output : 4194304
//   [4194304)   neg_output : 4194304
//   [8388608)   pos_attn   : 67108864
//   [75497472)  neg_attn   : 67108864
// ---------------------------------------------------------------------------

#define M_ROWS 4096
#define EDIM   1024
#define NROWS  65536

#define OFF_POSO 0
#define OFF_NEGO 4194304
#define OFF_POSA 8388608
#define OFF_NEGA 75497472

__device__ float g_Q [M_ROWS * EDIM];
__device__ float g_K [M_ROWS * EDIM];
__device__ float g_V [M_ROWS * EDIM];
__device__ float g_O1[M_ROWS * EDIM];
__device__ float g_O2[M_ROWS * EDIM];

// ---------------------------------------------------------------------------
// helpers
// ---------------------------------------------------------------------------
__device__ __forceinline__ uint32_t f2tf(float f)
{
    uint32_t u;
    asm("cvt.rna.tf32.f32 %0, %1;" : "=r"(u) : "f"(f));
    return u;
}

__device__ __forceinline__ void mma8(float* c, const uint32_t* a, const uint32_t* b)
{
    asm volatile(
        "mma.sync.aligned.m16n8k8.row.col.f32.tf32.tf32.f32 "
        "{%0,%1,%2,%3},{%4,%5,%6,%7},{%8,%9},{%0,%1,%2,%3};"
        : "+f"(c[0]), "+f"(c[1]), "+f"(c[2]), "+f"(c[3])
        : "r"(a[0]), "r"(a[1]), "r"(a[2]), "r"(a[3]), "r"(b[0]), "r"(b[1]));
}

// ---------------------------------------------------------------------------
// Batched TF32 GEMM, double-buffered pipeline.
//   C = alpha * A @ op(B) + bias
//   A: row-major M x K (lda)
//   B_KN=false: B stored N x K  -> C = A @ B^T
//   B_KN=true : B stored K x N  -> C = A @ B
// Per-z offsets: off = (z/16)*s1 + (z%16)*s2
// ---------------------------------------------------------------------------
template<int BM, int BN, int BK, int WM, int WN, bool B_KN>
__global__ void __launch_bounds__((BM / WM) * (BN / WN) * 32, 1)
gemm_tc(const float* __restrict__ A, int lda, long long sA1, long long sA2,
        const float* __restrict__ B, int ldb, long long sB1, long long sB2,
        const float* __restrict__ bias,
        float* __restrict__ C, int ldc, long long sC1, long long sC2,
        int Kdim, float alpha)
{
    constexpr int WARPS_M = BM / WM;
    constexpr int WARPS_N = BN / WN;
    constexpr int NTHREADS = WARPS_M * WARPS_N * 32;
    constexpr int MT = WM / 16;
    constexpr int NT = WN / 8;
    constexpr int PAD = 4;
    constexpr int BROWS = B_KN ? BK : BN;
    constexpr int BCOLS = (B_KN ? BN : BK) + PAD;
    constexpr int A_LD = BM * BK / 4 / NTHREADS;       // float4 per thread
    constexpr int B_LD = (B_KN ? BK * BN : BN * BK) / 4 / NTHREADS;

    const int z = blockIdx.z;
    A += (long long)(z >> 4) * sA1 + (long long)(z & 15) * sA2;
    B += (long long)(z >> 4) * sB1 + (long long)(z & 15) * sB2;
    C += (long long)(z >> 4) * sC1 + (long long)(z & 15) * sC2;

    __shared__ __align__(16) uint32_t As[2][BM][BK + PAD];
    __shared__ __align__(16) uint32_t Bs[2][BROWS][BCOLS];

    const int tid  = threadIdx.x;
    const int lane = tid & 31;
    const int warp = tid >> 5;
    const int wm = warp / WARPS_N;
    const int wn = warp % WARPS_N;
    const int row0 = blockIdx.y * BM;
    const int col0 = blockIdx.x * BN;

    float acc[MT][NT][4] = {};
    float4 areg[A_LD], breg[B_LD];

    // ---- global loads for K-tile at offset kk -> registers ----
    auto ldg_tile = [&](int kk) {
#pragma unroll
        for (int t = 0; t < A_LD; t++) {
            int i  = tid + t * NTHREADS;
            int r  = i / (BK / 4);
            int c4 = i % (BK / 4);
            areg[t] = *(const float4*)&A[(size_t)(row0 + r) * lda + kk + c4 * 4];
        }
        if (!B_KN) {
#pragma unroll
            for (int t = 0; t < B_LD; t++) {
                int i  = tid + t * NTHREADS;
                int r  = i / (BK / 4);
                int c4 = i % (BK / 4);
                breg[t] = *(const float4*)&B[(size_t)(col0 + r) * ldb + kk + c4 * 4];
            }
        } else {
#pragma unroll
            for (int t = 0; t < B_LD; t++) {
                int i  = tid + t * NTHREADS;
                int r  = i / (BN / 4);
                int c4 = i % (BN / 4);
                breg[t] = *(const float4*)&B[(size_t)(kk + r) * ldb + col0 + c4 * 4];
            }
        }
    };

    // ---- registers -> smem buffer (with tf32 convert) ----
    auto sts_tile = [&](int buf) {
#pragma unroll
        for (int t = 0; t < A_LD; t++) {
            int i  = tid + t * NTHREADS;
            int r  = i / (BK / 4);
            int c4 = i % (BK / 4);
            uint4 u = make_uint4(f2tf(areg[t].x), f2tf(areg[t].y),
                                 f2tf(areg[t].z), f2tf(areg[t].w));
            *(uint4*)&As[buf][r][c4 * 4] = u;
        }
#pragma unroll
        for (int t = 0; t < B_LD; t++) {
            int i  = tid + t * NTHREADS;
            int r  = i / ((B_KN ? BN : BK) / 4);
            int c4 = i % ((B_KN ? BN : BK) / 4);
            uint4 u = make_uint4(f2tf(breg[t].x), f2tf(breg[t].y),
                                 f2tf(breg[t].z), f2tf(breg[t].w));
            *(uint4*)&Bs[buf][r][c4 * 4] = u;
        }
    };

    // ---- mma over one staged K-tile ----
    auto mma_tile = [&](int buf) {
#pragma unroll
        for (int ks = 0; ks < BK; ks += 8) {
            uint32_t af[MT][4];
            uint32_t bf[NT][2];
#pragma unroll
            for (int mt = 0; mt < MT; mt++) {
                int m0 = wm * WM + mt * 16;
                af[mt][0] = As[buf][m0 + (lane >> 2)    ][ks + (lane & 3)    ];
                af[mt][1] = As[buf][m0 + (lane >> 2) + 8][ks + (lane & 3)    ];
                af[mt][2] = As[buf][m0 + (lane >> 2)    ][ks + (lane & 3) + 4];
                af[mt][3] = As[buf][m0 + (lane >> 2) + 8][ks + (lane & 3) + 4];
            }
#pragma unroll
            for (int nt = 0; nt < NT; nt++) {
                int n0 = wn * WN + nt * 8;
                if (!B_KN) {
                    bf[nt][0] = Bs[buf][n0 + (lane >> 2)][ks + (lane & 3)    ];
                    bf[nt][1] = Bs[buf][n0 + (lane >> 2)][ks + (lane & 3) + 4];
                } else {
                    bf[nt][0] = Bs[buf][ks + (lane & 3)    ][n0 + (lane >> 2)];
                    bf[nt][1] = Bs[buf][ks + (lane & 3) + 4][n0 + (lane >> 2)];
                }
            }
#pragma unroll
            for (int mt = 0; mt < MT; mt++)
#pragma unroll
                for (int nt = 0; nt < NT; nt++)
                    mma8(acc[mt][nt], af[mt], bf[nt]);
        }
    };

    // ---- pipelined mainloop: 1 sync per K-tile ----
    ldg_tile(0);
    sts_tile(0);
    __syncthreads();

    int buf = 0;
    for (int kk = BK; kk < Kdim; kk += BK) {
        ldg_tile(kk);          // overlap global latency with mma below
        mma_tile(buf);
        sts_tile(buf ^ 1);
        __syncthreads();
        buf ^= 1;
    }
    mma_tile(buf);

    // ---- epilogue ----
#pragma unroll
    for (int mt = 0; mt < MT; mt++) {
#pragma unroll
        for (int nt = 0; nt < NT; nt++) {
            int r = row0 + wm * WM + mt * 16 + (lane >> 2);
            int c = col0 + wn * WN + nt * 8 + 2 * (lane & 3);
            float b0 = bias ? bias[c]     : 0.0f;
            float b1 = bias ? bias[c + 1] : 0.0f;
            C[(size_t)r * ldc + c]           = acc[mt][nt][0] * alpha + b0;
            C[(size_t)r * ldc + c + 1]       = acc[mt][nt][1] * alpha + b1;
            C[(size_t)(r + 8) * ldc + c]     = acc[mt][nt][2] * alpha + b0;
            C[(size_t)(r + 8) * ldc + c + 1] = acc[mt][nt][3] * alpha + b1;
        }
    }
}

// ---------------------------------------------------------------------------
// Warp-per-row softmax + neg chain, fully in registers (no barriers).
// ---------------------------------------------------------------------------
__global__ void softmax_neg_kernel(float* __restrict__ pos,
                                   float* __restrict__ neg)
{
    const int warp = threadIdx.x >> 5;
    const int lane = threadIdx.x & 31;
    const size_t rid = (size_t)blockIdx.x * 8 + warp;
    float* prow = pos + rid * 1024;
    float* nrow = neg + rid * 1024;

    float v[32];
#pragma unroll
    for (int j = 0; j < 32; j++) v[j] = prow[j * 32 + lane];

    float m = -1e30f;
#pragma unroll
    for (int j = 0; j < 32; j++) m = fmaxf(m, v[j]);
#pragma unroll
    for (int s = 16; s > 0; s >>= 1) m = fmaxf(m, __shfl_xor_sync(0xffffffffu, m, s));

    float sum = 0.f;
#pragma unroll
    for (int j = 0; j < 32; j++) { v[j] = __expf(v[j] - m); sum += v[j]; }
#pragma unroll
    for (int s = 16; s > 0; s >>= 1) sum += __shfl_xor_sync(0xffffffffu, sum, s);
    const float inv = 1.0f / sum;

    float s1 = 0.f;
#pragma unroll
    for (int j = 0; j < 32; j++) { v[j] *= inv; s1 += 1.0f - v[j]; }
#pragma unroll
    for (int s = 16; s > 0; s >>= 1) s1 += __shfl_xor_sync(0xffffffffu, s1, s);
    const float invS1 = 1.0f / s1;

    float s2 = 0.f;
#pragma unroll
    for (int j = 0; j < 32; j++) {
        float p = v[j];
        prow[j * 32 + lane] = p;                       // final pos_attn
        float n = fminf((1.0f - p) * invS1, 1e-6f / (p + 1e-10f));
        v[j] = n;
        s2 += n;
    }
#pragma unroll
    for (int s = 16; s > 0; s >>= 1) s2 += __shfl_xor_sync(0xffffffffu, s2, s);
    const float inv2 = 1.0f / s2;

#pragma unroll
    for (int j = 0; j < 32; j++)
        nrow[j * 32 + lane] = v[j] * inv2;             // final neg_attn
}

// ---------------------------------------------------------------------------
// Launch
// ---------------------------------------------------------------------------
extern "C" void kernel_launch(void* const* d_in, const int* in_sizes, int n_in,
                              void* d_out, int out_size)
{
    const float* query = (const float*)d_in[0];
    const float* key   = (const float*)d_in[1];
    const float* value = (const float*)d_in[2];
    const float* Wq    = (const float*)d_in[3];
    const float* bq    = (const float*)d_in[4];
    const float* Wk    = (const float*)d_in[5];
    const float* bk    = (const float*)d_in[6];
    const float* Wv    = (const float*)d_in[7];
    const float* bv    = (const float*)d_in[8];
    const float* Wo    = (const float*)d_in[9];
    const float* bo    = (const float*)d_in[10];
    float* out = (float*)d_out;

    float *Q, *K, *V, *O1, *O2;
    cudaGetSymbolAddress((void**)&Q,  g_Q);
    cudaGetSymbolAddress((void**)&K,  g_K);
    cudaGetSymbolAddress((void**)&V,  g_V);
    cudaGetSymbolAddress((void**)&O1, g_O1);
    cudaGetSymbolAddress((void**)&O2, g_O2);

    // -------- projections: [4096,1024] = X @ W^T + b --------
    dim3 gproj(EDIM / 128, M_ROWS / 128, 1);   // (8, 32)
    gemm_tc<128,128,32,64,32,false><<<gproj, 256>>>(
        query, EDIM, 0, 0,  Wq, EDIM, 0, 0,  bq,  Q, EDIM, 0, 0,  EDIM, 1.0f);
    gemm_tc<128,128,32,64,32,false><<<gproj, 256>>>(
        key,   EDIM, 0, 0,  Wk, EDIM, 0, 0,  bk,  K, EDIM, 0, 0,  EDIM, 1.0f);
    gemm_tc<128,128,32,64,32,false><<<gproj, 256>>>(
        value, EDIM, 0, 0,  Wv, EDIM, 0, 0,  bv,  V, EDIM, 0, 0,  EDIM, 1.0f);

    // -------- scores: per (b,h) Q K^T / 8 -> pos_attn region --------
    gemm_tc<128,128,32,64,32,false><<<dim3(8, 8, 64), 256>>>(
        Q, EDIM, 1048576, 64,
        K, EDIM, 1048576, 64,
        nullptr,
        out + OFF_POSA, 1024, 16777216, 1048576,
        64, 0.125f);

    // -------- softmax + neg chain --------
    softmax_neg_kernel<<<NROWS / 8, 256>>>(out + OFF_POSA, out + OFF_NEGA);

    // -------- attn @ V (pos and neg) --------
    gemm_tc<64,64,32,32,32,true><<<dim3(1, 16, 64), 128>>>(
        out + OFF_POSA, 1024, 16777216, 1048576,
        V, EDIM, 1048576, 64,
        nullptr,
        O1, EDIM, 1048576, 64,
        1024, 1.0f);
    gemm_tc<64,64,32,32,32,true><<<dim3(1, 16, 64), 128>>>(
        out + OFF_NEGA, 1024, 16777216, 1048576,
        V, EDIM, 1048576, 64,
        nullptr,
        O2, EDIM, 1048576, 64,
        1024, 1.0f);

    // -------- output projection --------
    gemm_tc<128,128,32,64,32,false><<<gproj, 256>>>(
        O1, EDIM, 0, 0,  Wo, EDIM, 0, 0,  bo,  out + OFF_POSO, EDIM, 0, 0,  EDIM, 1.0f);
    gemm_tc<128,128,32,64,32,false><<<gproj, 256>>>(
        O2, EDIM, 0, 0,  Wo, EDIM, 0, 0,  bo,  out + OFF_NEGO, EDIM, 0, 0,  EDIM, 1.0f);
}